// round 14
// baseline (speedup 1.0000x reference)
#include <cuda_runtime.h>
#include <cstdint>

// CVXPolicy_Integrator, round 14: producer/consumer CTA specialization.
// 148 producer CTAs (GEMM1+tanh -> g_H fp16) + 148 consumer CTAs (GEMM2+
// Lambert -> out), 2 CTAs/SM co-resident, handoff via L2-resident g_H and
// release/acquire flags. Producers never wait on consumers (deadlock-free).

#define Bq 131072
#define Dq 256
#define Hq 100
#define NPROD 148
#define GRID  (2 * NPROD)
#define NT 256
#define NTILES (Bq / 128)

#define W1SW 136           // w1t row stride u32 (136%32==8)
#define XSW  24            // xs row stride u32 (24%32==24)
#define XBUF (128 * XSW)   // 3072 u32 per chunk slot
#define HPU  56            // h row width u32 (112 halves)

// ---- producer smem layout (u32) ----
#define P_W1  0
#define P_XS  (104 * W1SW)           // 14144
#define P_F32 (P_XS + 3 * XBUF)      // 23360: w1r0[104] b1s[104] tss[2][128]
#define P_END (P_F32 + 104 + 104 + 256)
// ---- consumer smem layout (u32) ----
#define C_W2  0
#define C_HS  (256 * HPU)            // 14336
#define C_F32 (C_HS + 2 * 64 * HPU)  // 21504: b2s[256] r2acc[64] scs[64]
#define C_END (C_F32 + 256 + 64 + 64)
#define SMEMU (P_END > C_END ? P_END : C_END)
#define SMEMT (SMEMU * 4)            // ~95.3 KB

__device__ unsigned g_H[(size_t)Bq * HPU];   // zero-initialized (.bss)
__device__ int g_flags[NTILES];              // zero-initialized

// ---------------- helpers ----------------
__device__ __forceinline__ unsigned pack_h2(float lo, float hi) {
    unsigned u;
    asm("cvt.rn.f16x2.f32 %0, %1, %2;" : "=r"(u) : "f"(hi), "f"(lo));
    return u;
}
__device__ __forceinline__ void mma_f16(float* c,
                                        unsigned a0, unsigned a1, unsigned a2, unsigned a3,
                                        unsigned b0, unsigned b1) {
    asm volatile(
        "mma.sync.aligned.m16n8k16.row.col.f32.f16.f16.f32 "
        "{%0,%1,%2,%3}, {%4,%5,%6,%7}, {%8,%9}, {%0,%1,%2,%3};"
        : "+f"(c[0]), "+f"(c[1]), "+f"(c[2]), "+f"(c[3])
        : "r"(a0), "r"(a1), "r"(a2), "r"(a3), "r"(b0), "r"(b1));
}
__device__ __forceinline__ void cp_async16(void* sdst, const void* gsrc) {
    unsigned s = (unsigned)__cvta_generic_to_shared(sdst);
    asm volatile("cp.async.cg.shared.global [%0], [%1], 16;" :: "r"(s), "l"(gsrc));
}
#define CP_COMMIT() asm volatile("cp.async.commit_group;")
#define CP_WAIT0()  asm volatile("cp.async.wait_group 0;")

__device__ __forceinline__ int permu(int u) {
    return (u & ~7) | ((u & 3) << 1) | ((u >> 2) & 1);
}

union F2U { float2 f; unsigned long long u; };
__device__ __forceinline__ float2 add2(float2 a, float2 b) {
    F2U A, B, C; A.f = a; B.f = b;
    asm("add.rn.f32x2 %0, %1, %2;" : "=l"(C.u) : "l"(A.u), "l"(B.u));
    return C.f;
}
__device__ __forceinline__ float2 fma2(float2 a, float2 b, float2 c) {
    F2U A, B, C, D; A.f = a; B.f = b; C.f = c;
    asm("fma.rn.f32x2 %0, %1, %2, %3;" : "=l"(D.u) : "l"(A.u), "l"(B.u), "l"(C.u));
    return D.f;
}
__device__ __forceinline__ float2 mul2(float2 a, float2 b) {
    F2U A, B, C; A.f = a; B.f = b;
    asm("mul.rn.f32x2 %0, %1, %2;" : "=l"(C.u) : "l"(A.u), "l"(B.u));
    return C.f;
}
__device__ __forceinline__ float tanh_fast(float x) {
    float ax = fabsf(x);
    float e  = __expf(-2.0f * ax);
    float th = 1.0f - __fdividef(2.0f * e, 1.0f + e);
    return copysignf(th, x);
}
__device__ __forceinline__ void spin_flag(const int* p) {
    int v;
    do {
        asm volatile("ld.acquire.gpu.b32 %0, [%1];" : "=r"(v) : "l"(p) : "memory");
        if (!v) __nanosleep(64);
    } while (!v);
}

__global__ void __launch_bounds__(NT, 2)
fused_policy(const float* __restrict__ z, const float* __restrict__ t,
             const float* __restrict__ W1, const float* __restrict__ b1,
             const float* __restrict__ W2, const float* __restrict__ b2,
             float* __restrict__ out)
{
    extern __shared__ unsigned sm[];
    const int tid = threadIdx.x;
    const int bid = blockIdx.x;
    const int warp = tid >> 5, lane = tid & 31;
    const int gid = lane >> 2, tig = lane & 3;

    if (bid < NPROD) {
        // ================= PRODUCER: h = tanh([z,t]@W1+b1) -> g_H =================
        unsigned* w1t = sm + P_W1;
        unsigned* xs  = sm + P_XS;
        float* w1r0 = (float*)(sm + P_F32);
        float* b1s  = w1r0 + 104;
        float* tss  = b1s + 104;    // [2][128]

        for (int idx = tid; idx < 128 * 104; idx += NT) {
            int u = idx / 104, n = idx - u * 104;
            float f0 = 0.f, f1 = 0.f;
            if (n < Hq) { f0 = W1[(2 * u + 1) * Hq + n]; f1 = W1[(2 * u + 2) * Hq + n]; }
            w1t[n * W1SW + permu(u)] = pack_h2(f0, f1);
        }
        if (tid < 104) {
            w1r0[tid] = (tid < Hq) ? W1[tid] : 0.f;
            b1s[tid]  = (tid < Hq) ? b1[tid] : 0.f;
        }

        const int m0 = (warp & 1) * 64;
        const int ngp = warp >> 1;                 // 4 n-groups over 13 n-tiles
        const int tb  = ngp ? (1 + 3 * ngp) : 0;   // {0,4,7,10}
        const int ntc = ngp ? 3 : 4;               // {4,3,3,3}
        const int mr  = m0 + gid;
        const int sr = tid >> 1, sb = tid & 1;     // staging: row, 16-col half

        int pt = bid, pc = 0;
        float4 rA = make_float4(0, 0, 0, 0), rB = rA, rC = rA, rD = rA;

        #define P_LDG() do {                                                     \
            if (pt < NTILES) {                                                   \
                const float4* src = (const float4*)z                             \
                    + ((size_t)(pt * 128 + sr)) * 64 + pc * 8 + sb * 4;          \
                rA = src[0]; rB = src[1]; rC = src[2]; rD = src[3];              \
            }                                                                    \
            pc++; if (pc == 8) { pc = 0; pt += NPROD; }                          \
        } while (0)

        #define P_STS(slot) do {                                                 \
            unsigned* d = xs + (slot) * XBUF + sr * XSW + sb * 8;                \
            uint4 u0, u1;                                                        \
            u0.x = pack_h2(rA.x, rA.y); u0.y = pack_h2(rC.x, rC.y);              \
            u0.z = pack_h2(rA.z, rA.w); u0.w = pack_h2(rC.z, rC.w);              \
            u1.x = pack_h2(rB.x, rB.y); u1.y = pack_h2(rD.x, rD.y);              \
            u1.z = pack_h2(rB.z, rB.w); u1.w = pack_h2(rD.z, rD.w);              \
            *(uint4*)d = u0; *(uint4*)(d + 4) = u1;                              \
        } while (0)

        P_LDG();            // chunk 0 -> regs
        P_STS(0);           // chunk 0 -> slot 0
        P_LDG();            // chunk 1 -> regs
        __syncthreads();
        int ss = 1, ms = 0, par = 0;

        float acc[4][4][4];
        #pragma unroll
        for (int nt = 0; nt < 4; nt++)
            #pragma unroll
            for (int mf = 0; mf < 4; mf++)
                #pragma unroll
                for (int i = 0; i < 4; i++) acc[nt][mf][i] = 0.f;

        for (int tile = bid; tile < NTILES; tile += NPROD) {
            if (tid < 128) tss[par * 128 + tid] = t[tile * 128 + tid];

            #pragma unroll
            for (int s = 0; s < 8; s++) {
                P_STS(ss); ss = (ss == 2) ? 0 : ss + 1;   // chunk G+1
                P_LDG();                                  // chunk G+2
                __syncthreads();                          // chunk G visible
                const unsigned* xa = xs + ms * XBUF + mr * XSW + 2 * tig;
                const unsigned* wb = w1t + (tb * 8 + gid) * W1SW + s * 16 + 2 * tig;
                #pragma unroll
                for (int ks = 0; ks < 2; ks++) {
                    const int u0 = ks * 8;
                    uint2 A0 = *(const uint2*)(xa + u0);
                    uint2 A1 = *(const uint2*)(xa + 8 * XSW + u0);
                    uint2 A2 = *(const uint2*)(xa + 16 * XSW + u0);
                    uint2 A3 = *(const uint2*)(xa + 24 * XSW + u0);
                    uint2 A4 = *(const uint2*)(xa + 32 * XSW + u0);
                    uint2 A5 = *(const uint2*)(xa + 40 * XSW + u0);
                    uint2 A6 = *(const uint2*)(xa + 48 * XSW + u0);
                    uint2 A7 = *(const uint2*)(xa + 56 * XSW + u0);
                    #pragma unroll
                    for (int nt = 0; nt < 4; nt++) {
                        if (nt < ntc) {
                            uint2 bb = *(const uint2*)(wb + nt * 8 * W1SW + u0);
                            mma_f16(acc[nt][0], A0.x, A1.x, A0.y, A1.y, bb.x, bb.y);
                            mma_f16(acc[nt][1], A2.x, A3.x, A2.y, A3.y, bb.x, bb.y);
                            mma_f16(acc[nt][2], A4.x, A5.x, A4.y, A5.y, bb.x, bb.y);
                            mma_f16(acc[nt][3], A6.x, A7.x, A6.y, A7.y, bb.x, bb.y);
                        }
                    }
                }
                ms = (ms == 2) ? 0 : ms + 1;
            }

            // epilogue1: bias + t*W1row0 + tanh -> g_H (fp16, k-permuted)
            const size_t rowbase = (size_t)tile * 128;
            #pragma unroll
            for (int nt = 0; nt < 4; nt++) {
                if (nt < ntc) {
                    int u = (tb + nt) * 4 + tig;
                    int col = 2 * u, pos = permu(u);
                    float bb0 = b1s[col], bb1 = b1s[col + 1];
                    float w0 = w1r0[col], w1v = w1r0[col + 1];
                    #pragma unroll
                    for (int j = 0; j < 8; j++) {
                        int row = mr + 8 * j;
                        float tv = tss[par * 128 + row];
                        float a0 = acc[nt][j >> 1][(j & 1) * 2]     + bb0;
                        float a1 = acc[nt][j >> 1][(j & 1) * 2 + 1] + bb1;
                        g_H[(rowbase + row) * HPU + pos] =
                            pack_h2(tanh_fast(fmaf(tv, w0, a0)), tanh_fast(fmaf(tv, w1v, a1)));
                    }
                    #pragma unroll
                    for (int mf = 0; mf < 4; mf++)
                        acc[nt][mf][0] = acc[nt][mf][1] = acc[nt][mf][2] = acc[nt][mf][3] = 0.f;
                }
            }
            __threadfence();
            __syncthreads();
            if (tid == 0)
                asm volatile("st.release.gpu.b32 [%0], %1;"
                             :: "l"(&g_flags[tile]), "r"(1) : "memory");
            par ^= 1;
        }
    } else {
        // ================= CONSUMER: p = h@W2+b2; Lambert; ustar =================
        unsigned* w2t = sm + C_W2;
        unsigned* hs  = sm + C_HS;
        float* b2s   = (float*)(sm + C_F32);
        float* r2acc = b2s + 256;
        float* scs   = r2acc + 64;

        const int cid = bid - NPROD;

        for (int idx = tid; idx < HPU * Dq; idx += NT) {
            int u = idx >> 8, n = idx & 255;
            int k0 = 2 * u;
            float f0 = (k0 < Hq) ? W2[k0 * Dq + n] : 0.f;
            float f1 = (k0 + 1 < Hq) ? W2[(k0 + 1) * Dq + n] : 0.f;
            w2t[n * HPU + permu(u)] = pack_h2(f0, f1);
        }
        if (tid < Dq) b2s[tid] = b2[tid];
        if (tid < 64) r2acc[tid] = 0.f;

        const int m0 = (warp & 1) * 32;
        const int ngc = warp >> 1;
        const int n0 = ngc * 64;
        const int mr = m0 + gid;

        #define C_ISSUE(bufi, tl, sb_) do {                                      \
            const uint4* src = (const uint4*)(g_H + ((size_t)(tl) * 128 + (sb_) * 64) * HPU); \
            unsigned* dst = hs + (bufi) * (64 * HPU);                            \
            _Pragma("unroll")                                                    \
            for (int j = 0; j < 4; j++) {                                        \
                int idx = j * NT + tid;                                          \
                if (idx < 64 * HPU / 4) cp_async16(dst + idx * 4, src + idx);    \
            }                                                                    \
        } while (0)

        int buf = 0;
        spin_flag(&g_flags[cid]);
        C_ISSUE(0, cid, 0);
        CP_COMMIT();

        for (int tile = cid; tile < NTILES; tile += NPROD) {
            #pragma unroll 1
            for (int sub = 0; sub < 2; sub++) {
                CP_WAIT0();
                __syncthreads();
                // prefetch next subtile (spin only when crossing to a new tile)
                {
                    int ntile = sub ? tile + NPROD : tile;
                    int nsub = sub ^ 1;
                    if (ntile < NTILES) {
                        if (nsub == 0) spin_flag(&g_flags[ntile]);
                        C_ISSUE(buf ^ 1, ntile, nsub);
                    }
                }
                CP_COMMIT();

                float a2c[8][2][4];
                #pragma unroll
                for (int nt = 0; nt < 8; nt++)
                    #pragma unroll
                    for (int mf = 0; mf < 2; mf++)
                        #pragma unroll
                        for (int i = 0; i < 4; i++) a2c[nt][mf][i] = 0.f;

                const unsigned* ha = hs + buf * (64 * HPU) + mr * HPU + 2 * tig;
                const unsigned* wb2 = w2t + (n0 + gid) * HPU + 2 * tig;
                #pragma unroll
                for (int ks = 0; ks < 7; ks++) {
                    const int u0 = ks * 8;
                    uint2 A0 = *(const uint2*)(ha + u0);
                    uint2 A1 = *(const uint2*)(ha + 8 * HPU + u0);
                    uint2 A2 = *(const uint2*)(ha + 16 * HPU + u0);
                    uint2 A3 = *(const uint2*)(ha + 24 * HPU + u0);
                    #pragma unroll
                    for (int nt = 0; nt < 8; nt++) {
                        uint2 bb = *(const uint2*)(wb2 + nt * 8 * HPU + u0);
                        mma_f16(a2c[nt][0], A0.x, A1.x, A0.y, A1.y, bb.x, bb.y);
                        mma_f16(a2c[nt][1], A2.x, A3.x, A2.y, A3.y, bb.x, bb.y);
                    }
                }

                // epi2: bias + r2 + Lambert + scale + store
                float2 S0 = make_float2(0.f, 0.f), S1 = S0, S2 = S0, S3 = S0;
                #pragma unroll
                for (int nt = 0; nt < 8; nt++) {
                    int col = n0 + nt * 8 + 2 * tig;
                    float2 b01 = *(const float2*)&b2s[col];
                    float2 v0 = add2(make_float2(a2c[nt][0][0], a2c[nt][0][1]), b01);
                    float2 v1 = add2(make_float2(a2c[nt][0][2], a2c[nt][0][3]), b01);
                    float2 v2 = add2(make_float2(a2c[nt][1][0], a2c[nt][1][1]), b01);
                    float2 v3 = add2(make_float2(a2c[nt][1][2], a2c[nt][1][3]), b01);
                    S0 = fma2(v0, v0, S0); S1 = fma2(v1, v1, S1);
                    S2 = fma2(v2, v2, S2); S3 = fma2(v3, v3, S3);
                    a2c[nt][0][0] = v0.x; a2c[nt][0][1] = v0.y;
                    a2c[nt][0][2] = v1.x; a2c[nt][0][3] = v1.y;
                    a2c[nt][1][0] = v2.x; a2c[nt][1][1] = v2.y;
                    a2c[nt][1][2] = v3.x; a2c[nt][1][3] = v3.y;
                }
                float s0 = S0.x + S0.y, s1 = S1.x + S1.y;
                float s2 = S2.x + S2.y, s3 = S3.x + S3.y;
                s0 += __shfl_xor_sync(0xffffffffu, s0, 1); s0 += __shfl_xor_sync(0xffffffffu, s0, 2);
                s1 += __shfl_xor_sync(0xffffffffu, s1, 1); s1 += __shfl_xor_sync(0xffffffffu, s1, 2);
                s2 += __shfl_xor_sync(0xffffffffu, s2, 1); s2 += __shfl_xor_sync(0xffffffffu, s2, 2);
                s3 += __shfl_xor_sync(0xffffffffu, s3, 1); s3 += __shfl_xor_sync(0xffffffffu, s3, 2);
                if (tig == 0) {
                    atomicAdd(&r2acc[mr],      s0);
                    atomicAdd(&r2acc[mr + 8],  s1);
                    atomicAdd(&r2acc[mr + 16], s2);
                    atomicAdd(&r2acc[mr + 24], s3);
                }
                __syncthreads();

                if (tid < 64) {
                    float rr2 = r2acc[tid];
                    r2acc[tid] = 0.f;
                    float w = log1pf(rr2);
                    #pragma unroll
                    for (int it = 0; it < 10; it++) {
                        float ew  = __expf(w);
                        float num = fmaf(w, ew, -rr2);
                        float den = fmaf(w, ew, ew);
                        w = w - __fdividef(num, den);
                    }
                    w = fmaxf(w, 0.0f);
                    float tn = sqrtf(w);
                    float rr = sqrtf(rr2);
                    float scale = (rr > 1e-12f) ? __fdividef(tn, fmaxf(rr, 1e-12f)) : 1.0f;
                    scs[tid] = -scale;
                }
                __syncthreads();

                const float2 sc0 = make_float2(scs[mr], scs[mr]);
                const float2 sc1 = make_float2(scs[mr + 8], scs[mr + 8]);
                const float2 sc2 = make_float2(scs[mr + 16], scs[mr + 16]);
                const float2 sc3 = make_float2(scs[mr + 24], scs[mr + 24]);
                const size_t rb = ((size_t)(tile * 128 + sub * 64 + mr)) * Dq;
                #pragma unroll
                for (int nt = 0; nt < 8; nt++) {
                    int col = n0 + nt * 8 + 2 * tig;
                    *(float2*)&out[rb + col]           = mul2(sc0, make_float2(a2c[nt][0][0], a2c[nt][0][1]));
                    *(float2*)&out[rb + 8  * Dq + col] = mul2(sc1, make_float2(a2c[nt][0][2], a2c[nt][0][3]));
                    *(float2*)&out[rb + 16 * Dq + col] = mul2(sc2, make_float2(a2c[nt][1][0], a2c[nt][1][1]));
                    *(float2*)&out[rb + 24 * Dq + col] = mul2(sc3, make_float2(a2c[nt][1][2], a2c[nt][1][3]));
                }
                buf ^= 1;
            }
        }
    }
}

// ---------------- launch ----------------
extern "C" void kernel_launch(void* const* d_in, const int* in_sizes, int n_in,
                              void* d_out, int out_size)
{
    const float* z  = (const float*)d_in[0];
    const float* t  = (const float*)d_in[1];
    const float* W1 = (const float*)d_in[2];
    const float* b1 = (const float*)d_in[3];
    const float* W2 = (const float*)d_in[4];
    const float* b2 = (const float*)d_in[5];
    float* out = (float*)d_out;

    cudaFuncSetAttribute(fused_policy, cudaFuncAttributeMaxDynamicSharedMemorySize, SMEMT);
    fused_policy<<<GRID, NT, SMEMT>>>(z, t, W1, b1, W2, b2, out);
}